// round 3
// baseline (speedup 1.0000x reference)
#include <cuda_runtime.h>
#include <math.h>

#define BB 4
#define SS 64
#define DD 512
#define HH 8
#define DH 64
#define DFF 2048
#define LL 2
#define VV 32128
#define TT 16

// ---------------- scratch (device globals; no runtime allocation) ----------------
__device__ float g_x[BB*SS*DD];
__device__ float g_h[BB*SS*DD];
__device__ float g_q[BB*SS*DD];
__device__ float g_k[BB*SS*DD];
__device__ float g_v[BB*SS*DD];
__device__ float g_ao[BB*SS*DD];
__device__ float g_ffn[BB*SS*DFF];
__device__ float g_hs[BB*SS*DD];
__device__ float g_kc[LL*BB*SS*DD];   // cross-attn K per layer
__device__ float g_vc[LL*BB*SS*DD];   // cross-attn V per layer
__device__ float g_ksc[LL*BB*TT*DD];  // self-attn K cache
__device__ float g_vsc[LL*BB*TT*DD];  // self-attn V cache
__device__ float g_dx[BB*DD];
__device__ float g_dq[BB*DD];
__device__ float g_da[BB*DD];
__device__ float g_dffn[BB*DFF];
__device__ float g_logits[BB*VV];
__device__ float g_probs[BB*VV];
__device__ float g_bias[BB*SS];

__device__ __forceinline__ float warpSum(float v) {
#pragma unroll
    for (int o = 16; o > 0; o >>= 1) v += __shfl_xor_sync(0xffffffffu, v, o);
    return v;
}

// ---------------- embedding gather + encoder bias ----------------
__global__ void k_embed(const int* __restrict__ ids, const float* __restrict__ emb,
                        const float* __restrict__ mask) {
    int row = blockIdx.x;  // b*SS + s
    int id = ids[row];
    const float* e = emb + (size_t)id * DD;
    for (int d = threadIdx.x; d < DD; d += blockDim.x) g_x[row * DD + d] = e[d];
    if (threadIdx.x == 0) g_bias[row] = (1.0f - mask[row]) * -1e9f;
}

// ---------------- rmsnorm over rows of [rows, DD] ----------------
__global__ void k_rmsnorm(const float* __restrict__ x, const float* __restrict__ w,
                          float* __restrict__ out) {
    int row = blockIdx.x;
    const float* xr = x + (size_t)row * DD;
    float ss = 0.f;
    for (int i = threadIdx.x; i < DD; i += 256) { float v = xr[i]; ss += v * v; }
    ss = warpSum(ss);
    __shared__ float red[8];
    __shared__ float sscale;
    int lane = threadIdx.x & 31, wid = threadIdx.x >> 5;
    if (lane == 0) red[wid] = ss;
    __syncthreads();
    if (threadIdx.x == 0) {
        float s = 0.f;
        for (int i = 0; i < 8; i++) s += red[i];
        sscale = rsqrtf(s * (1.0f / DD) + 1e-6f);
    }
    __syncthreads();
    float sc = sscale;
    for (int i = threadIdx.x; i < DD; i += 256) out[(size_t)row * DD + i] = xr[i] * sc * w[i];
}

// ---------------- tiled GEMM: C[M,N] = A[M,K] @ W[K,N] (+res)(+relu) ----------------
__global__ void k_gemm(const float* __restrict__ A, const float* __restrict__ W,
                       const float* __restrict__ res, float* __restrict__ C,
                       int M, int N, int K, int doRelu) {
    __shared__ __align__(16) float As[16][64];
    __shared__ __align__(16) float Ws[16][64];
    int tid = threadIdx.x;
    int tx = tid & 15, ty = tid >> 4;
    int bm = blockIdx.y * 64, bn = blockIdx.x * 64;
    int ar = tid >> 2, ac = (tid & 3) * 4;
    int wr = tid >> 4, wc = (tid & 15) * 4;
    float acc[4][4] = {};
    for (int k0 = 0; k0 < K; k0 += 16) {
        float4 av = *(const float4*)(A + (size_t)(bm + ar) * K + k0 + ac);
        As[ac + 0][ar] = av.x; As[ac + 1][ar] = av.y; As[ac + 2][ar] = av.z; As[ac + 3][ar] = av.w;
        *(float4*)&Ws[wr][wc] = *(const float4*)(W + (size_t)(k0 + wr) * N + bn + wc);
        __syncthreads();
#pragma unroll
        for (int kk = 0; kk < 16; kk++) {
            float4 a = *(const float4*)&As[kk][ty * 4];
            float4 b = *(const float4*)&Ws[kk][tx * 4];
            acc[0][0] += a.x * b.x; acc[0][1] += a.x * b.y; acc[0][2] += a.x * b.z; acc[0][3] += a.x * b.w;
            acc[1][0] += a.y * b.x; acc[1][1] += a.y * b.y; acc[1][2] += a.y * b.z; acc[1][3] += a.y * b.w;
            acc[2][0] += a.z * b.x; acc[2][1] += a.z * b.y; acc[2][2] += a.z * b.z; acc[2][3] += a.z * b.w;
            acc[3][0] += a.w * b.x; acc[3][1] += a.w * b.y; acc[3][2] += a.w * b.z; acc[3][3] += a.w * b.w;
        }
        __syncthreads();
    }
#pragma unroll
    for (int i = 0; i < 4; i++) {
        int m = bm + ty * 4 + i;
#pragma unroll
        for (int j = 0; j < 4; j++) {
            int n = bn + tx * 4 + j;
            float v = acc[i][j];
            if (res) v += res[(size_t)m * N + n];
            if (doRelu) v = fmaxf(v, 0.f);
            C[(size_t)m * N + n] = v;
        }
    }
}

// ---------------- encoder attention: one block per (b,h,i), 64 threads ----------------
__global__ void k_enc_attn(const float* __restrict__ q, const float* __restrict__ k,
                           const float* __restrict__ v, float* __restrict__ out) {
    int bi = blockIdx.x;
    int i = bi & 63; int h = (bi >> 6) & 7; int b = bi >> 9;
    int tid = threadIdx.x;
    __shared__ float qs[DH];
    __shared__ float at[SS];
    qs[tid] = q[(size_t)(b * SS + i) * DD + h * DH + tid];
    __syncthreads();
    const float* kr = k + (size_t)(b * SS + tid) * DD + h * DH;
    float dot = 0.f;
#pragma unroll
    for (int d = 0; d < DH; d++) dot += qs[d] * kr[d];
    at[tid] = dot * 0.125f + g_bias[b * SS + tid];
    __syncthreads();
    float m = -1e30f;
    for (int j = 0; j < SS; j++) m = fmaxf(m, at[j]);
    __syncthreads();
    at[tid] = expf(at[tid] - m);
    __syncthreads();
    float s = 0.f;
    for (int j = 0; j < SS; j++) s += at[j];
    float inv = 1.0f / s;
    const float* vb = v + (size_t)b * SS * DD + h * DH + tid;
    float o = 0.f;
    for (int j = 0; j < SS; j++) o += at[j] * vb[(size_t)j * DD];
    out[(size_t)(b * SS + i) * DD + h * DH + tid] = o * inv;
}

// ---------------- decoder init: x = emb[PAD_ID=0] ----------------
__global__ void k_dec_init(const float* __restrict__ emb) {
    int i = blockIdx.x * blockDim.x + threadIdx.x;
    if (i < BB * DD) g_dx[i] = emb[i & (DD - 1)];
}

// ---------------- fused rmsnorm into shared (blockDim=256) ----------------
__device__ __forceinline__ void load_norm(const float* __restrict__ x,
                                          const float* __restrict__ lnw,
                                          float* sh_h /* BB*DD */) {
    int tid = threadIdx.x;
    float ss[BB] = {0.f, 0.f, 0.f, 0.f};
    for (int i = tid; i < DD; i += 256) {
#pragma unroll
        for (int b = 0; b < BB; b++) {
            float v = x[b * DD + i];
            sh_h[b * DD + i] = v;
            ss[b] += v * v;
        }
    }
    __shared__ float sred[BB][8];
    __shared__ float sscale[BB];
    int lane = tid & 31, wid = tid >> 5;
#pragma unroll
    for (int b = 0; b < BB; b++) {
        float v = warpSum(ss[b]);
        if (lane == 0) sred[b][wid] = v;
    }
    __syncthreads();
    if (tid < BB) {
        float s = 0.f;
        for (int w = 0; w < 8; w++) s += sred[tid][w];
        sscale[tid] = rsqrtf(s * (1.0f / DD) + 1e-6f);
    }
    __syncthreads();
    for (int i = tid; i < DD; i += 256) {
        float w = lnw[i];
#pragma unroll
        for (int b = 0; b < BB; b++) sh_h[b * DD + i] *= sscale[b] * w;
    }
    __syncthreads();
}

// ---------------- fused norm + GEMV: out[B,N] = rmsnorm(x) @ W[DD,N] ----------------
__global__ void k_gemv_norm(const float* __restrict__ x, const float* __restrict__ lnw,
                            const float* __restrict__ W, float* __restrict__ out,
                            int N, int doRelu) {
    __shared__ float sh_h[BB * DD];
    load_norm(x, lnw, sh_h);
    int col = blockIdx.x * 256 + threadIdx.x;
    if (col >= N) return;
    float acc[BB] = {0.f, 0.f, 0.f, 0.f};
#pragma unroll 8
    for (int k = 0; k < DD; k++) {
        float wv = W[(size_t)k * N + col];
#pragma unroll
        for (int b = 0; b < BB; b++) acc[b] += sh_h[b * DD + k] * wv;
    }
#pragma unroll
    for (int b = 0; b < BB; b++) {
        float v = acc[b];
        if (doRelu) v = fmaxf(v, 0.f);
        out[(size_t)b * N + col] = v;
    }
}

// ---------------- fused norm + QKV GEMV with KV-cache append ----------------
__global__ void k_gemv_norm_qkv(const float* __restrict__ x, const float* __restrict__ lnw,
                                const float* __restrict__ Wq, const float* __restrict__ Wk,
                                const float* __restrict__ Wv,
                                float* __restrict__ outq, float* __restrict__ kc,
                                float* __restrict__ vc, int t) {
    __shared__ float sh_h[BB * DD];
    load_norm(x, lnw, sh_h);
    int which = blockIdx.x >> 1;
    int col = (blockIdx.x & 1) * 256 + threadIdx.x;
    const float* W = (which == 0) ? Wq : ((which == 1) ? Wk : Wv);
    float acc[BB] = {0.f, 0.f, 0.f, 0.f};
#pragma unroll 8
    for (int k = 0; k < DD; k++) {
        float wv = W[(size_t)k * DD + col];
#pragma unroll
        for (int b = 0; b < BB; b++) acc[b] += sh_h[b * DD + k] * wv;
    }
    if (which == 0) {
#pragma unroll
        for (int b = 0; b < BB; b++) outq[b * DD + col] = acc[b];
    } else {
        float* c = (which == 1) ? kc : vc;
#pragma unroll
        for (int b = 0; b < BB; b++) c[(size_t)(b * TT + t) * DD + col] = acc[b];
    }
}

// ---------------- GEMV + residual accumulate (split-K via atomics) ----------------
__global__ void k_gemv_res(const float* __restrict__ A, const float* __restrict__ W,
                           float* __restrict__ x, int K, int N) {
    __shared__ float sh_a[BB * 512];
    int KS = gridDim.y;
    int Kc = K / KS;
    int k0 = blockIdx.y * Kc;
    for (int i = threadIdx.x; i < Kc; i += 256) {
#pragma unroll
        for (int b = 0; b < BB; b++) sh_a[b * Kc + i] = A[(size_t)b * K + k0 + i];
    }
    __syncthreads();
    int col = blockIdx.x * 256 + threadIdx.x;
    if (col >= N) return;
    float acc[BB] = {0.f, 0.f, 0.f, 0.f};
#pragma unroll 8
    for (int i = 0; i < Kc; i++) {
        float wv = W[(size_t)(k0 + i) * N + col];
#pragma unroll
        for (int b = 0; b < BB; b++) acc[b] += sh_a[b * Kc + i] * wv;
    }
#pragma unroll
    for (int b = 0; b < BB; b++) atomicAdd(&x[(size_t)b * N + col], acc[b]);
}

// ---------------- decoder self-attention (last row, KV cache) ----------------
__global__ void k_dec_self(const float* __restrict__ kc, const float* __restrict__ vc, int t) {
    int h = blockIdx.x & 7, b = blockIdx.x >> 3;
    int tid = threadIdx.x;
    __shared__ float qs[DH];
    __shared__ float at[TT];
    qs[tid] = g_dq[b * DD + h * DH + tid];
    __syncthreads();
    int nk = t + 1;
    if (tid < nk) {
        const float* kr = kc + (size_t)(b * TT + tid) * DD + h * DH;
        float dot = 0.f;
#pragma unroll
        for (int d = 0; d < DH; d++) dot += qs[d] * kr[d];
        at[tid] = dot * 0.125f;
    }
    __syncthreads();
    float m = -1e30f;
    for (int j = 0; j < nk; j++) m = fmaxf(m, at[j]);
    __syncthreads();
    if (tid < nk) at[tid] = expf(at[tid] - m);
    __syncthreads();
    float s = 0.f;
    for (int j = 0; j < nk; j++) s += at[j];
    const float* vb = vc + (size_t)b * TT * DD + h * DH + tid;
    float o = 0.f;
    for (int j = 0; j < nk; j++) o += at[j] * vb[(size_t)j * DD];
    g_da[b * DD + h * DH + tid] = o / s;
}

// ---------------- decoder cross-attention (S=64 keys) ----------------
__global__ void k_dec_cross(const float* __restrict__ kc, const float* __restrict__ vc) {
    int h = blockIdx.x & 7, b = blockIdx.x >> 3;
    int tid = threadIdx.x;
    __shared__ float qs[DH];
    __shared__ float at[SS];
    qs[tid] = g_dq[b * DD + h * DH + tid];
    __syncthreads();
    const float* kr = kc + (size_t)(b * SS + tid) * DD + h * DH;
    float dot = 0.f;
#pragma unroll
    for (int d = 0; d < DH; d++) dot += qs[d] * kr[d];
    at[tid] = dot * 0.125f + g_bias[b * SS + tid];
    __syncthreads();
    float m = -1e30f;
    for (int j = 0; j < SS; j++) m = fmaxf(m, at[j]);
    __syncthreads();
    at[tid] = expf(at[tid] - m);
    __syncthreads();
    float s = 0.f;
    for (int j = 0; j < SS; j++) s += at[j];
    const float* vb = vc + (size_t)b * SS * DD + h * DH + tid;
    float o = 0.f;
    for (int j = 0; j < SS; j++) o += at[j] * vb[(size_t)j * DD];
    g_da[b * DD + h * DH + tid] = o / s;
}

// ---------------- softmax + argmax + output write + zero y-accumulator ----------------
__global__ void k_softmax_out(float* __restrict__ outp, float* __restrict__ outf, int t) {
    int b = blockIdx.x, tid = threadIdx.x;  // 1024 threads
    const float* lg = g_logits + (size_t)b * VV;
    float m = -3e38f; int mi = 0;
    for (int v = tid; v < VV; v += 1024) {
        float xv = lg[v];
        if (xv > m) { m = xv; mi = v; }
    }
    int lane = tid & 31, wid = tid >> 5;
#pragma unroll
    for (int o = 16; o > 0; o >>= 1) {
        float om = __shfl_down_sync(0xffffffffu, m, o);
        int oi = __shfl_down_sync(0xffffffffu, mi, o);
        if (om > m || (om == m && oi < mi)) { m = om; mi = oi; }
    }
    __shared__ float sm[32]; __shared__ int si[32];
    if (lane == 0) { sm[wid] = m; si[wid] = mi; }
    __syncthreads();
    if (wid == 0) {
        m = sm[lane]; mi = si[lane];
#pragma unroll
        for (int o = 16; o > 0; o >>= 1) {
            float om = __shfl_down_sync(0xffffffffu, m, o);
            int oi = __shfl_down_sync(0xffffffffu, mi, o);
            if (om > m || (om == m && oi < mi)) { m = om; mi = oi; }
        }
        if (lane == 0) { sm[0] = m; si[0] = mi; }
    }
    __syncthreads();
    m = sm[0];
    int amax = si[0];
    float s = 0.f;
    float* pb = g_probs + (size_t)b * VV;
    for (int v = tid; v < VV; v += 1024) {
        float e = expf(lg[v] - m);
        pb[v] = e;
        s += e;
    }
    s = warpSum(s);
    __shared__ float sr[32];
    __shared__ float stot;
    if (lane == 0) sr[wid] = s;
    __syncthreads();
    if (tid == 0) {
        float tot = 0.f;
        for (int w = 0; w < 32; w++) tot += sr[w];
        stot = tot;
    }
    __syncthreads();
    float inv = 1.0f / stot;
    float* op = outp + ((size_t)b * TT + t) * VV;
    for (int v = tid; v < VV; v += 1024) {
        float p = pb[v] * inv;
        pb[v] = p;
        op[v] = p;
    }
    if (tid == 0 && outf) outf[b * TT + t] = (amax == 0) ? 1.0f : 0.0f;
    for (int d = tid; d < DD; d += 1024) g_dx[b * DD + d] = 0.f;
}

// ---------------- soft embedding: y[B,D] += probs[B,V] @ emb[V,D] ----------------
#define VCH 502  // 64 * 502 == 32128 exactly
__global__ void k_probs_emb(const float* __restrict__ emb) {
    __shared__ float sp[BB * VCH];
    int tid = threadIdx.x;
    int c0 = blockIdx.y * VCH;
    for (int i = tid; i < VCH; i += 256) {
#pragma unroll
        for (int b = 0; b < BB; b++) sp[b * VCH + i] = g_probs[(size_t)b * VV + c0 + i];
    }
    __syncthreads();
    int col = blockIdx.x * 256 + tid;
    float acc[BB] = {0.f, 0.f, 0.f, 0.f};
#pragma unroll 4
    for (int i = 0; i < VCH; i++) {
        float wv = emb[(size_t)(c0 + i) * DD + col];
#pragma unroll
        for (int b = 0; b < BB; b++) acc[b] += sp[b * VCH + i] * wv;
    }
#pragma unroll
    for (int b = 0; b < BB; b++) atomicAdd(&g_dx[b * DD + col], acc[b]);
}

// ============================================================================
extern "C" void kernel_launch(void* const* d_in, const int* in_sizes, int n_in,
                              void* d_out, int out_size) {
    const int*   ids  = (const int*)d_in[0];
    const float* mask = (const float*)d_in[1];
    const float* emb  = (const float*)d_in[2];
    const float* ewq  = (const float*)d_in[3];
    const float* ewk  = (const float*)d_in[4];
    const float* ewv  = (const float*)d_in[5];
    const float* ewo  = (const float*)d_in[6];
    const float* eln1 = (const float*)d_in[7];
    const float* ew1  = (const float*)d_in[8];
    const float* ew2  = (const float*)d_in[9];
    const float* eln2 = (const float*)d_in[10];
    const float* elnf = (const float*)d_in[11];
    const float* dsq  = (const float*)d_in[12];
    const float* dsk  = (const float*)d_in[13];
    const float* dsv  = (const float*)d_in[14];
    const float* dso  = (const float*)d_in[15];
    const float* dln1 = (const float*)d_in[16];
    const float* dcq  = (const float*)d_in[17];
    const float* dck  = (const float*)d_in[18];
    const float* dcv  = (const float*)d_in[19];
    const float* dco  = (const float*)d_in[20];
    const float* dln2 = (const float*)d_in[21];
    const float* dw1  = (const float*)d_in[22];
    const float* dw2  = (const float*)d_in[23];
    const float* dln3 = (const float*)d_in[24];
    const float* dlnf = (const float*)d_in[25];
    const float* lmh  = (const float*)d_in[26];

    float* outp = (float*)d_out;
    float* outf = (out_size >= BB * TT * VV + BB * TT) ? (outp + (size_t)BB * TT * VV) : nullptr;

    void* p;
    cudaGetSymbolAddress(&p, g_x);      float* px    = (float*)p;
    cudaGetSymbolAddress(&p, g_h);      float* ph    = (float*)p;
    cudaGetSymbolAddress(&p, g_q);      float* pq    = (float*)p;
    cudaGetSymbolAddress(&p, g_k);      float* pk    = (float*)p;
    cudaGetSymbolAddress(&p, g_v);      float* pv    = (float*)p;
    cudaGetSymbolAddress(&p, g_ao);     float* pao   = (float*)p;
    cudaGetSymbolAddress(&p, g_ffn);    float* pffn  = (float*)p;
    cudaGetSymbolAddress(&p, g_hs);     float* phs   = (float*)p;
    cudaGetSymbolAddress(&p, g_kc);     float* pkc   = (float*)p;
    cudaGetSymbolAddress(&p, g_vc);     float* pvc   = (float*)p;
    cudaGetSymbolAddress(&p, g_ksc);    float* pksc  = (float*)p;
    cudaGetSymbolAddress(&p, g_vsc);    float* pvsc  = (float*)p;
    cudaGetSymbolAddress(&p, g_dx);     float* pdx   = (float*)p;
    cudaGetSymbolAddress(&p, g_dq);     float* pdq   = (float*)p;
    cudaGetSymbolAddress(&p, g_da);     float* pda   = (float*)p;
    cudaGetSymbolAddress(&p, g_dffn);   float* pdffn = (float*)p;
    cudaGetSymbolAddress(&p, g_logits); float* plg   = (float*)p;

    const int M = BB * SS;  // 256
    dim3 gD(DD / 64, M / 64);      // (8, 4)
    dim3 gF(DFF / 64, M / 64);     // (32, 4)

    // ---------------- encoder ----------------
    k_embed<<<BB * SS, 128>>>(ids, emb, mask);
    for (int l = 0; l < LL; l++) {
        size_t o2 = (size_t)l * DD * DD;
        k_rmsnorm<<<M, 256>>>(px, eln1 + l * DD, ph);
        k_gemm<<<gD, 256>>>(ph, ewq + o2, nullptr, pq, M, DD, DD, 0);
        k_gemm<<<gD, 256>>>(ph, ewk + o2, nullptr, pk, M, DD, DD, 0);
        k_gemm<<<gD, 256>>>(ph, ewv + o2, nullptr, pv, M, DD, DD, 0);
        k_enc_attn<<<BB * HH * SS, 64>>>(pq, pk, pv, pao);
        k_gemm<<<gD, 256>>>(pao, ewo + o2, px, px, M, DD, DD, 0);
        k_rmsnorm<<<M, 256>>>(px, eln2 + l * DD, ph);
        k_gemm<<<gF, 256>>>(ph, ew1 + (size_t)l * DD * DFF, nullptr, pffn, M, DFF, DD, 1);
        k_gemm<<<gD, 256>>>(pffn, ew2 + (size_t)l * DFF * DD, px, px, M, DD, DFF, 0);
    }
    k_rmsnorm<<<M, 256>>>(px, elnf, phs);
    for (int l = 0; l < LL; l++) {
        size_t o2 = (size_t)l * DD * DD;
        k_gemm<<<gD, 256>>>(phs, dck + o2, nullptr, pkc + (size_t)l * BB * SS * DD, M, DD, DD, 0);
        k_gemm<<<gD, 256>>>(phs, dcv + o2, nullptr, pvc + (size_t)l * BB * SS * DD, M, DD, DD, 0);
    }

    // ---------------- decoder (incremental, KV-cached — exact vs full recompute) ------
    k_dec_init<<<(BB * DD + 255) / 256, 256>>>(emb);
    for (int t = 0; t < TT; t++) {
        for (int l = 0; l < LL; l++) {
            size_t o2 = (size_t)l * DD * DD;
            float* ksl = pksc + (size_t)l * BB * TT * DD;
            float* vsl = pvsc + (size_t)l * BB * TT * DD;
            k_gemv_norm_qkv<<<6, 256>>>(pdx, dln1 + l * DD, dsq + o2, dsk + o2, dsv + o2,
                                        pdq, ksl, vsl, t);
            k_dec_self<<<BB * HH, 64>>>(ksl, vsl, t);
            k_gemv_res<<<dim3(2, 4), 256>>>(pda, dso + o2, pdx, DD, DD);
            k_gemv_norm<<<2, 256>>>(pdx, dln2 + l * DD, dcq + o2, pdq, DD, 0);
            k_dec_cross<<<BB * HH, 64>>>(pkc + (size_t)l * BB * SS * DD,
                                         pvc + (size_t)l * BB * SS * DD);
            k_gemv_res<<<dim3(2, 4), 256>>>(pda, dco + o2, pdx, DD, DD);
            k_gemv_norm<<<8, 256>>>(pdx, dln3 + l * DD, dw1 + (size_t)l * DD * DFF, pdffn, DFF, 1);
            k_gemv_res<<<dim3(2, 4), 256>>>(pdffn, dw2 + (size_t)l * DFF * DD, pdx, DFF, DD);
        }
        k_gemv_norm<<<(VV + 255) / 256, 256>>>(pdx, dlnf, lmh, plg, VV, 0);
        k_softmax_out<<<BB, 1024>>>(outp, outf, t);
        if (t + 1 < TT) k_probs_emb<<<dim3(2, 64), 256>>>(emb);
    }
}

// round 4
// speedup vs baseline: 3.4587x; 3.4587x over previous
#include <cuda_runtime.h>
#include <math.h>

#define BB 4
#define SS 64
#define DD 512
#define HH 8
#define DH 64
#define DFF 2048
#define LL 2
#define VV 32128
#define TT 16

// ---------------- scratch (device globals) ----------------
__device__ float g_x[BB*SS*DD];
__device__ float g_h[BB*SS*DD];
__device__ float g_qkv[3*BB*SS*DD];      // q|k|v contiguous (single zero target)
__device__ float g_ao[BB*SS*DD];
__device__ float g_ffn[BB*SS*DFF];
__device__ float g_hs[BB*SS*DD];
__device__ float g_ckv[2*LL*BB*SS*DD];   // [l][k|v][B*S*D]
__device__ float g_ksc[LL*BB*TT*DD];
__device__ float g_vsc[LL*BB*TT*DD];
__device__ float g_dx[BB*DD];
__device__ float g_dq[BB*DD];
__device__ float g_da[BB*DD];
__device__ float g_dffn[BB*DFF];
__device__ float g_logits[BB*VV];
__device__ float g_probs[BB*VV];
__device__ float g_bias[BB*SS];

__device__ __forceinline__ float warpSum(float v) {
#pragma unroll
    for (int o = 16; o > 0; o >>= 1) v += __shfl_xor_sync(0xffffffffu, v, o);
    return v;
}

// ---------------- embedding gather + encoder bias ----------------
__global__ void k_embed(const int* __restrict__ ids, const float* __restrict__ emb,
                        const float* __restrict__ mask) {
    int row = blockIdx.x;
    int id = ids[row];
    const float* e = emb + (size_t)id * DD;
    for (int d = threadIdx.x; d < DD; d += blockDim.x) g_x[row * DD + d] = e[d];
    if (threadIdx.x == 0) g_bias[row] = (1.0f - mask[row]) * -1e9f;
}

// ---------------- rmsnorm rows [M, DD] + fused buffer zeroing ----------------
__global__ void k_rmsnorm(const float* __restrict__ x, const float* __restrict__ w,
                          float* __restrict__ out, float* __restrict__ zbuf, int zn) {
    int row = blockIdx.x;
    const float* xr = x + (size_t)row * DD;
    float ss = 0.f;
    for (int i = threadIdx.x; i < DD; i += 256) { float v = xr[i]; ss += v * v; }
    ss = warpSum(ss);
    __shared__ float red[8];
    __shared__ float sscale;
    int lane = threadIdx.x & 31, wid = threadIdx.x >> 5;
    if (lane == 0) red[wid] = ss;
    __syncthreads();
    if (threadIdx.x == 0) {
        float s = 0.f;
        for (int i = 0; i < 8; i++) s += red[i];
        sscale = rsqrtf(s * (1.0f / DD) + 1e-6f);
    }
    __syncthreads();
    float sc = sscale;
    for (int i = threadIdx.x; i < DD; i += 256) out[(size_t)row * DD + i] = xr[i] * sc * w[i];
    if (zbuf) {
        int stride = gridDim.x * 256;
        for (int i = blockIdx.x * 256 + threadIdx.x; i < zn; i += stride) zbuf[i] = 0.f;
    }
}

// ---------------- encoder GEMM: split-K + up-to-3-matrix fusion, atomic epilogue ------
// C[mat] += A @ W[mat], 64x64 tiles, grid (N/64, M/64, nmat*KS). Targets pre-zeroed
// or residual-valued. reluA applies relu on the A operand at load (for w2 after ffn1).
__global__ void k_egemm3(const float* __restrict__ A,
                         const float* __restrict__ W0, const float* __restrict__ W1,
                         const float* __restrict__ W2,
                         float* __restrict__ C0, float* __restrict__ C1,
                         float* __restrict__ C2,
                         int N, int K, int KS, int reluA) {
    __shared__ __align__(16) float As[16][64];
    __shared__ __align__(16) float Ws[16][64];
    int zz = blockIdx.z;
    int mat = zz / KS, ks = zz - mat * KS;
    const float* W = (mat == 0) ? W0 : ((mat == 1) ? W1 : W2);
    float* C = (mat == 0) ? C0 : ((mat == 1) ? C1 : C2);
    int Kc = K / KS;
    int kbeg = ks * Kc;
    int tid = threadIdx.x;
    int tx = tid & 15, ty = tid >> 4;
    int bm = blockIdx.y * 64, bn = blockIdx.x * 64;
    int ar = tid >> 2, ac = (tid & 3) * 4;
    int wr = tid >> 4, wc = (tid & 15) * 4;
    float acc[4][4] = {};
    for (int k0 = kbeg; k0 < kbeg + Kc; k0 += 16) {
        float4 av = *(const float4*)(A + (size_t)(bm + ar) * K + k0 + ac);
        if (reluA) {
            av.x = fmaxf(av.x, 0.f); av.y = fmaxf(av.y, 0.f);
            av.z = fmaxf(av.z, 0.f); av.w = fmaxf(av.w, 0.f);
        }
        As[ac + 0][ar] = av.x; As[ac + 1][ar] = av.y; As[ac + 2][ar] = av.z; As[ac + 3][ar] = av.w;
        *(float4*)&Ws[wr][wc] = *(const float4*)(W + (size_t)(k0 + wr) * N + bn + wc);
        __syncthreads();
#pragma unroll
        for (int kk = 0; kk < 16; kk++) {
            float4 a = *(const float4*)&As[kk][ty * 4];
            float4 b = *(const float4*)&Ws[kk][tx * 4];
            acc[0][0] += a.x * b.x; acc[0][1] += a.x * b.y; acc[0][2] += a.x * b.z; acc[0][3] += a.x * b.w;
            acc[1][0] += a.y * b.x; acc[1][1] += a.y * b.y; acc[1][2] += a.y * b.z; acc[1][3] += a.y * b.w;
            acc[2][0] += a.z * b.x; acc[2][1] += a.z * b.y; acc[2][2] += a.z * b.z; acc[2][3] += a.z * b.w;
            acc[3][0] += a.w * b.x; acc[3][1] += a.w * b.y; acc[3][2] += a.w * b.z; acc[3][3] += a.w * b.w;
        }
        __syncthreads();
    }
#pragma unroll
    for (int i = 0; i < 4; i++) {
        int m = bm + ty * 4 + i;
#pragma unroll
        for (int j = 0; j < 4; j++) {
            atomicAdd(&C[(size_t)m * N + bn + tx * 4 + j], acc[i][j]);
        }
    }
}

// ---------------- encoder attention: one block per (b,h,i), 64 threads ----------------
__global__ void k_enc_attn(const float* __restrict__ q, const float* __restrict__ k,
                           const float* __restrict__ v, float* __restrict__ out) {
    int bi = blockIdx.x;
    int i = bi & 63; int h = (bi >> 6) & 7; int b = bi >> 9;
    int tid = threadIdx.x;
    __shared__ float qs[DH];
    __shared__ float at[SS];
    qs[tid] = q[(size_t)(b * SS + i) * DD + h * DH + tid];
    __syncthreads();
    const float* kr = k + (size_t)(b * SS + tid) * DD + h * DH;
    float dot = 0.f;
#pragma unroll
    for (int d = 0; d < DH; d++) dot += qs[d] * kr[d];
    at[tid] = dot * 0.125f + g_bias[b * SS + tid];
    __syncthreads();
    float m = -1e30f;
    for (int j = 0; j < SS; j++) m = fmaxf(m, at[j]);
    __syncthreads();
    at[tid] = expf(at[tid] - m);
    __syncthreads();
    float s = 0.f;
    for (int j = 0; j < SS; j++) s += at[j];
    float inv = 1.0f / s;
    const float* vb = v + (size_t)b * SS * DD + h * DH + tid;
    float o = 0.f;
    for (int j = 0; j < SS; j++) o += at[j] * vb[(size_t)j * DD];
    out[(size_t)(b * SS + i) * DD + h * DH + tid] = o * inv;
}

// ---------------- decoder init: x = emb[PAD_ID=0] ----------------
__global__ void k_dec_init(const float* __restrict__ emb) {
    int i = blockIdx.x * blockDim.x + threadIdx.x;
    if (i < BB * DD) g_dx[i] = emb[i & (DD - 1)];
}

// ---------------- fused rmsnorm into shared (blockDim=256) ----------------
__device__ __forceinline__ void load_norm(const float* __restrict__ x,
                                          const float* __restrict__ lnw,
                                          float* sh_h /* BB*DD */) {
    int tid = threadIdx.x;
    float ss[BB] = {0.f, 0.f, 0.f, 0.f};
    for (int i = tid; i < DD; i += 256) {
#pragma unroll
        for (int b = 0; b < BB; b++) {
            float v = x[b * DD + i];
            sh_h[b * DD + i] = v;
            ss[b] += v * v;
        }
    }
    __shared__ float sred[BB][8];
    __shared__ float sscale[BB];
    int lane = tid & 31, wid = tid >> 5;
#pragma unroll
    for (int b = 0; b < BB; b++) {
        float v = warpSum(ss[b]);
        if (lane == 0) sred[b][wid] = v;
    }
    __syncthreads();
    if (tid < BB) {
        float s = 0.f;
        for (int w = 0; w < 8; w++) s += sred[tid][w];
        sscale[tid] = rsqrtf(s * (1.0f / DD) + 1e-6f);
    }
    __syncthreads();
    for (int i = tid; i < DD; i += 256) {
        float w = lnw[i];
#pragma unroll
        for (int b = 0; b < BB; b++) sh_h[b * DD + i] *= sscale[b] * w;
    }
    __syncthreads();
}

// ---------------- decode: norm + GEMV, in-block split-K (32 cols x 8 splits) ----------
__global__ void k_dgemv_norm(const float* __restrict__ x, const float* __restrict__ lnw,
                             const float* __restrict__ W, float* __restrict__ out,
                             int N, int doRelu) {
    __shared__ float sh[BB * DD];
    __shared__ float part[256 * BB];
    load_norm(x, lnw, sh);
    int tid = threadIdx.x;
    int c = tid & 31, s = tid >> 5;
    int col = blockIdx.x * 32 + c;
    float acc[BB] = {0.f, 0.f, 0.f, 0.f};
    const float* Wp = W + (size_t)(s * 64) * N + col;
#pragma unroll 8
    for (int i = 0; i < 64; i++) {
        float w = Wp[(size_t)i * N];
#pragma unroll
        for (int b = 0; b < BB; b++) acc[b] += sh[b * DD + s * 64 + i] * w;
    }
#pragma unroll
    for (int b = 0; b < BB; b++) part[tid * BB + b] = acc[b];
    __syncthreads();
    if (tid < 128) {
        int cc = tid & 31, b = tid >> 5;
        float t = 0.f;
#pragma unroll
        for (int s2 = 0; s2 < 8; s2++) t += part[(s2 * 32 + cc) * BB + b];
        if (doRelu) t = fmaxf(t, 0.f);
        out[(size_t)b * N + blockIdx.x * 32 + cc] = t;
    }
}

// ---------------- decode: norm + QKV GEMV with KV-cache append (grid.x = 48) ---------
__global__ void k_dgemv_qkv(const float* __restrict__ x, const float* __restrict__ lnw,
                            const float* __restrict__ Wq, const float* __restrict__ Wk,
                            const float* __restrict__ Wv,
                            float* __restrict__ outq, float* __restrict__ kc,
                            float* __restrict__ vc, int t) {
    __shared__ float sh[BB * DD];
    __shared__ float part[256 * BB];
    load_norm(x, lnw, sh);
    int mat = blockIdx.x >> 4;
    int cb = blockIdx.x & 15;
    const float* W = (mat == 0) ? Wq : ((mat == 1) ? Wk : Wv);
    int tid = threadIdx.x;
    int c = tid & 31, s = tid >> 5;
    int col = cb * 32 + c;
    float acc[BB] = {0.f, 0.f, 0.f, 0.f};
    const float* Wp = W + (size_t)(s * 64) * DD + col;
#pragma unroll 8
    for (int i = 0; i < 64; i++) {
        float w = Wp[(size_t)i * DD];
#pragma unroll
        for (int b = 0; b < BB; b++) acc[b] += sh[b * DD + s * 64 + i] * w;
    }
#pragma unroll
    for (int b = 0; b < BB; b++) part[tid * BB + b] = acc[b];
    __syncthreads();
    if (tid < 128) {
        int cc = tid & 31, b = tid >> 5;
        float tv = 0.f;
#pragma unroll
        for (int s2 = 0; s2 < 8; s2++) tv += part[(s2 * 32 + cc) * BB + b];
        int co = cb * 32 + cc;
        if (mat == 0) outq[b * DD + co] = tv;
        else {
            float* cch = (mat == 1) ? kc : vc;
            cch[(size_t)(b * TT + t) * DD + co] = tv;
        }
    }
}

// ---------------- decode: plain GEMV, accumulate into x (single owner per col) -------
template <int SPLIT>
__global__ void k_dgemv_acc(const float* __restrict__ A, const float* __restrict__ W,
                            float* __restrict__ x, int K) {
    constexpr int CPB = 256 / SPLIT;
    __shared__ float sh[BB * 2048];
    __shared__ float part[256 * BB];
    int tid = threadIdx.x;
    for (int i = tid; i < K; i += 256) {
#pragma unroll
        for (int b = 0; b < BB; b++) sh[b * K + i] = A[(size_t)b * K + i];
    }
    __syncthreads();
    int c = tid % CPB, s = tid / CPB;
    int col = blockIdx.x * CPB + c;
    int Kc = K / SPLIT;
    float acc[BB] = {0.f, 0.f, 0.f, 0.f};
    const float* Wp = W + (size_t)(s * Kc) * DD + col;
#pragma unroll 8
    for (int i = 0; i < Kc; i++) {
        float w = Wp[(size_t)i * DD];
#pragma unroll
        for (int b = 0; b < BB; b++) acc[b] += sh[b * K + s * Kc + i] * w;
    }
#pragma unroll
    for (int b = 0; b < BB; b++) part[tid * BB + b] = acc[b];
    __syncthreads();
    if (tid < CPB * BB) {
        int cc = tid % CPB, b = tid / CPB;
        float t = 0.f;
#pragma unroll
        for (int s2 = 0; s2 < SPLIT; s2++) t += part[(s2 * CPB + cc) * BB + b];
        x[b * DD + blockIdx.x * CPB + cc] += t;
    }
}

// ---------------- decoder self-attention (last row, KV cache) ----------------
__global__ void k_dec_self(const float* __restrict__ kc, const float* __restrict__ vc, int t) {
    int h = blockIdx.x & 7, b = blockIdx.x >> 3;
    int tid = threadIdx.x;
    __shared__ float qs[DH];
    __shared__ float at[TT];
    qs[tid] = g_dq[b * DD + h * DH + tid];
    __syncthreads();
    int nk = t + 1;
    if (tid < nk) {
        const float* kr = kc + (size_t)(b * TT + tid) * DD + h * DH;
        float dot = 0.f;
#pragma unroll
        for (int d = 0; d < DH; d++) dot += qs[d] * kr[d];
        at[tid] = dot * 0.125f;
    }
    __syncthreads();
    float m = -1e30f;
    for (int j = 0; j < nk; j++) m = fmaxf(m, at[j]);
    __syncthreads();
    if (tid < nk) at[tid] = expf(at[tid] - m);
    __syncthreads();
    float s = 0.f;
    for (int j = 0; j < nk; j++) s += at[j];
    const float* vb = vc + (size_t)b * TT * DD + h * DH + tid;
    float o = 0.f;
    for (int j = 0; j < nk; j++) o += at[j] * vb[(size_t)j * DD];
    g_da[b * DD + h * DH + tid] = o / s;
}

// ---------------- decoder cross-attention (S=64 keys) ----------------
__global__ void k_dec_cross(const float* __restrict__ kc, const float* __restrict__ vc) {
    int h = blockIdx.x & 7, b = blockIdx.x >> 3;
    int tid = threadIdx.x;
    __shared__ float qs[DH];
    __shared__ float at[SS];
    qs[tid] = g_dq[b * DD + h * DH + tid];
    __syncthreads();
    const float* kr = kc + (size_t)(b * SS + tid) * DD + h * DH;
    float dot = 0.f;
#pragma unroll
    for (int d = 0; d < DH; d++) dot += qs[d] * kr[d];
    at[tid] = dot * 0.125f + g_bias[b * SS + tid];
    __syncthreads();
    float m = -1e30f;
    for (int j = 0; j < SS; j++) m = fmaxf(m, at[j]);
    __syncthreads();
    at[tid] = expf(at[tid] - m);
    __syncthreads();
    float s = 0.f;
    for (int j = 0; j < SS; j++) s += at[j];
    const float* vb = vc + (size_t)b * SS * DD + h * DH + tid;
    float o = 0.f;
    for (int j = 0; j < SS; j++) o += at[j] * vb[(size_t)j * DD];
    g_da[b * DD + h * DH + tid] = o / s;
}

// ---------------- lm_head: norm + GEMV, float4 (128 cols/block), grid = 251 ----------
__global__ void k_lmh(const float* __restrict__ x, const float* __restrict__ lnw,
                      const float* __restrict__ W) {
    __shared__ float sh[BB * DD];
    __shared__ float4 part[256 * BB];
    load_norm(x, lnw, sh);
    int tid = threadIdx.x;
    int g = tid & 31, s = tid >> 5;
    int col = blockIdx.x * 128 + g * 4;
    float4 acc[BB];
#pragma unroll
    for (int b = 0; b < BB; b++) acc[b] = make_float4(0.f, 0.f, 0.f, 0.f);
    const float* Wp = W + (size_t)(s * 64) * VV + col;
#pragma unroll 4
    for (int i = 0; i < 64; i++) {
        float4 w = *(const float4*)(Wp + (size_t)i * VV);
#pragma unroll
        for (int b = 0; b < BB; b++) {
            float a = sh[b * DD + s * 64 + i];
            acc[b].x += a * w.x; acc[b].y += a * w.y;
            acc[b].z += a * w.z; acc[b].w += a * w.w;
        }
    }
#pragma unroll
    for (int b = 0; b < BB; b++) part[tid * BB + b] = acc[b];
    __syncthreads();
    if (tid < 128) {
        int gg = tid & 31, b = tid >> 5;
        float4 t = make_float4(0.f, 0.f, 0.f, 0.f);
#pragma unroll
        for (int s2 = 0; s2 < 8; s2++) {
            float4 p = part[(s2 * 32 + gg) * BB + b];
            t.x += p.x; t.y += p.y; t.z += p.z; t.w += p.w;
        }
        *(float4*)(g_logits + (size_t)b * VV + blockIdx.x * 128 + gg * 4) = t;
    }
}

// ---------------- softmax + argmax + output write + zero y-accumulator ----------------
__global__ void k_softmax_out(float* __restrict__ outp, float* __restrict__ outf, int t) {
    int b = blockIdx.x, tid = threadIdx.x;  // 1024 threads
    const float* lg = g_logits + (size_t)b * VV;
    float m = -3e38f; int mi = 0;
    for (int v = tid; v < VV; v += 1024) {
        float xv = lg[v];
        if (xv > m) { m = xv; mi = v; }
    }
    int lane = tid & 31, wid = tid >> 5;
#pragma unroll
    for (int o = 16; o > 0; o >>= 1) {
        float om = __shfl_down_sync(0xffffffffu, m, o);
        int oi = __shfl_down_sync(0xffffffffu, mi, o);
        if (om > m || (om == m && oi < mi)) { m = om; mi = oi; }
    }
    __shared__ float sm[32]; __shared__ int si[32];
    if (lane == 0) { sm[wid] = m; si[wid] = mi; }
    __syncthreads();
    if (wid == 0) {
        m = sm[lane]; mi = si[lane];
#pragma unroll
        for (int o = 16; o > 0; o >>= 1) {
            float om = __shfl_down_sync(0xffffffffu, m, o);
            int oi = __shfl_down_sync(0xffffffffu, mi, o);
            if (om > m || (om == m && oi < mi)) { m = om; mi = oi; }
        }
        if (lane == 0) { sm[0] = m; si[0] = mi; }
    }
    __syncthreads();
    m = sm[0];
    int amax = si[0];
    float s = 0.f;
    float* pb = g_probs + (size_t)b * VV;
    for (int v = tid; v < VV; v += 1024) {
        float e = expf(lg[v] - m);
        pb[v] = e;
        s += e;
    }
    s = warpSum(s);
    __shared__ float sr[32];
    __shared__ float stot;
    if (lane == 0) sr[wid] = s;
    __syncthreads();
    if (tid == 0) {
        float tot = 0.f;
        for (int w = 0; w < 32; w++) tot += sr[w];
        stot = tot;
    }
    __syncthreads();
    float inv = 1.0f / stot;
    float* op = outp + ((size_t)b * TT + t) * VV;
    for (int v = tid; v < VV; v += 1024) {
        float p = pb[v] * inv;
        pb[v] = p;
        op[v] = p;
    }
    if (tid == 0 && outf) outf[b * TT + t] = (amax == 0) ? 1.0f : 0.0f;
    for (int d = tid; d < DD; d += 1024) g_dx[b * DD + d] = 0.f;
}

// ---------------- soft embedding: y += probs @ emb, float4, grid (4, 64) -------------
#define VCH 502  // 64 * 502 == 32128
__global__ void k_probs_emb(const float* __restrict__ emb) {
    __shared__ float sp[BB * VCH];
    __shared__ float4 part[256 * BB];
    int tid = threadIdx.x;
    int c0 = blockIdx.y * VCH;
    for (int i = tid; i < VCH; i += 256) {
#pragma unroll
        for (int b = 0; b < BB; b++) sp[b * VCH + i] = g_probs[(size_t)b * VV + c0 + i];
    }
    __syncthreads();
    int g = tid & 31, s = tid >> 5;
    int col = blockIdx.x * 128 + g * 4;
    float4 acc[BB];
#pragma unroll
    for (int b = 0; b < BB; b++) acc[b] = make_float4(0.f, 0.f, 0.f, 0.f);
#pragma unroll 4
    for (int i = s; i < VCH; i += 8) {
        float4 e = *(const float4*)(emb + (size_t)(c0 + i) * DD + col);
#pragma unroll
        for (int b = 0; b < BB; b++) {
            float p = sp[b * VCH + i];
            acc[b].x += p * e.x; acc[b].y += p * e.y;
            acc[b].z += p * e.z; acc[b].w += p * e.w;
        }
    }
#pragma unroll
    for (int b = 0; b < BB; b++) part[tid * BB + b] = acc[b];
    __syncthreads();
    if (tid < 128) {
        int gg = tid & 31, b = tid >> 5;
        float4 t = make_float4(0.f, 0.f, 0.f, 0.f);
#pragma unroll
        for (int s2 = 0; s2 < 8; s2++) {
            float4 p = part[(s2 * 32 + gg) * BB + b];
            t.x += p.x; t.y += p.y; t.z += p.z; t.w += p.w;
        }
        int co = blockIdx.x * 128 + gg * 4;
        atomicAdd(&g_dx[b * DD + co + 0], t.x);
        atomicAdd(&g_dx[b * DD + co + 1], t.y);
        atomicAdd(&g_dx[b * DD + co + 2], t.z);
        atomicAdd(&g_dx[b * DD + co + 3], t.w);
    }
}

// ============================================================================
extern "C" void kernel_launch(void* const* d_in, const int* in_sizes, int n_in,
                              void* d_out, int out_size) {
    const int*   ids  = (const int*)d_in[0];
    const float* mask = (const float*)d_in[1];
    const float* emb  = (const float*)d_in[2];
    const float* ewq  = (const float*)d_in[3];
    const float* ewk  = (const float*)d_in[4];
    const float* ewv  = (const float*)d_in[5];
    const float* ewo  = (const float*)d_in[6];
    const float* eln1 = (const float*)d_in[7];
    const float* ew1  = (const float*)d_in[8];
    const float* ew2  = (const float*)d_in[9];
    const float* eln2 = (const float*)d_in[10];
    const float* elnf = (const float*)d_in[11];
    const float* dsq  = (const float*)d_in[12];
    const float* dsk  = (const float*)d_in[13];
    const float* dsv  = (const float*)d_in[14];
    const float* dso  = (const float*)d_in[15];
    const float* dln1 = (const float*)d_in[16];
    const float* dcq  = (const float*)d_in[17];
    const float* dck  = (const float*)d_in[18];
    const float* dcv  = (const float*)d_in[19];
    const float* dco  = (const float*)d_in[20];
    const float* dln2 = (const float*)d_in[21];
    const float* dw1  = (const float*)d_in[22];
    const float* dw2  = (const float*)d_in[23];
    const float* dln3 = (const float*)d_in[24];
    const float* dlnf = (const float*)d_in[25];
    const float* lmh  = (const float*)d_in[26];

    float* outp = (float*)d_out;
    float* outf = (out_size >= BB * TT * VV + BB * TT) ? (outp + (size_t)BB * TT * VV) : nullptr;

    void* p;
    cudaGetSymbolAddress(&p, g_x);      float* px    = (float*)p;
    cudaGetSymbolAddress(&p, g_h);      float* ph    = (float*)p;
    cudaGetSymbolAddress(&p, g_qkv);    float* pqkv  = (float*)p;
    cudaGetSymbolAddress(&p, g_ao);     float* pao   = (float*)p;
    cudaGetSymbolAddress(&p, g_ffn);    float* pffn  = (float*)p;
    cudaGetSymbolAddress(&p, g_hs);     float* phs   = (float*)p;
    cudaGetSymbolAddress(&p, g_ckv);    float* pckv  = (float*)p;
    cudaGetSymbolAddress(&p, g_ksc);    float* pksc  = (float*)p;
    cudaGetSymbolAddress(&p, g_vsc);    float* pvsc  = (float*)p;
    cudaGetSymbolAddress(&p, g_dx);     float* pdx   = (float*)p;
    cudaGetSymbolAddress(&p, g_dq);     float* pdq   = (float*)p;
    cudaGetSymbolAddress(&p, g_da);     float* pda   = (float*)p;
    cudaGetSymbolAddress(&p, g_dffn);   float* pdffn = (float*)p;

    const int M = BB * SS;          // 256
    const int MD = M * DD;          // 131072
    float* pq = pqkv;
    float* pk = pqkv + MD;
    float* pv = pqkv + 2 * MD;

    // ---------------- encoder ----------------
    k_embed<<<BB * SS, 128>>>(ids, emb, mask);
    for (int l = 0; l < LL; l++) {
        size_t o2 = (size_t)l * DD * DD;
        k_rmsnorm<<<M, 256>>>(px, eln1 + l * DD, ph, pqkv, 3 * MD);
        k_egemm3<<<dim3(8, 4, 6), 256>>>(ph, ewq + o2, ewk + o2, ewv + o2,
                                         pq, pk, pv, DD, DD, 2, 0);
        k_enc_attn<<<BB * HH * SS, 64>>>(pq, pk, pv, pao);
        k_egemm3<<<dim3(8, 4, 4), 256>>>(pao, ewo + o2, nullptr, nullptr,
                                         px, nullptr, nullptr, DD, DD, 4, 0);
        k_rmsnorm<<<M, 256>>>(px, eln2 + l * DD, ph, pffn, M * DFF);
        k_egemm3<<<dim3(32, 4, 2), 256>>>(ph, ew1 + (size_t)l * DD * DFF, nullptr, nullptr,
                                          pffn, nullptr, nullptr, DFF, DD, 2, 0);
        k_egemm3<<<dim3(8, 4, 8), 256>>>(pffn, ew2 + (size_t)l * DFF * DD, nullptr, nullptr,
                                         px, nullptr, nullptr, DD, DFF, 8, 1);
    }
    k_rmsnorm<<<M, 256>>>(px, elnf, phs, pckv, 2 * LL * MD);
    for (int l = 0; l < LL; l++) {
        size_t o2 = (size_t)l * DD * DD;
        float* kcl = pckv + (size_t)(l * 2 + 0) * MD;
        float* vcl = pckv + (size_t)(l * 2 + 1) * MD;
        k_egemm3<<<dim3(8, 4, 4), 256>>>(phs, dck + o2, dcv + o2, nullptr,
                                         kcl, vcl, nullptr, DD, DD, 2, 0);
    }

    // ---------------- decoder (incremental, KV-cached — exact) ----------------
    k_dec_init<<<(BB * DD + 255) / 256, 256>>>(emb);
    for (int t = 0; t < TT; t++) {
        for (int l = 0; l < LL; l++) {
            size_t o2 = (size_t)l * DD * DD;
            float* ksl = pksc + (size_t)l * BB * TT * DD;
            float* vsl = pvsc + (size_t)l * BB * TT * DD;
            float* kcl = pckv + (size_t)(l * 2 + 0) * MD;
            float* vcl = pckv + (size_t)(l * 2 + 1) * MD;
            k_dgemv_qkv<<<48, 256>>>(pdx, dln1 + l * DD, dsq + o2, dsk + o2, dsv + o2,
                                     pdq, ksl, vsl, t);
            k_dec_self<<<BB * HH, 64>>>(ksl, vsl, t);
            k_dgemv_acc<8><<<16, 256>>>(pda, dso + o2, pdx, DD);
            k_dgemv_norm<<<16, 256>>>(pdx, dln2 + l * DD, dcq + o2, pdq, DD, 0);
            k_dec_cross<<<BB * HH, 64>>>(kcl, vcl);
            k_dgemv_acc<8><<<16, 256>>>(pda, dco + o2, pdx, DD);
            k_dgemv_norm<<<64, 256>>>(pdx, dln3 + l * DD, dw1 + (size_t)l * DD * DFF,
                                      pdffn, DFF, 1);
            k_dgemv_acc<16><<<32, 256>>>(pdffn, dw2 + (size_t)l * DFF * DD, pdx, DFF);
        }
        k_lmh<<<VV / 128, 256>>>(pdx, dlnf, lmh);
        k_softmax_out<<<BB, 1024>>>(outp, outf, t);
        if (t + 1 < TT) k_probs_emb<<<dim3(4, 64), 256>>>(emb);
    }
}

// round 5
// speedup vs baseline: 4.8803x; 1.4110x over previous
#include <cuda_runtime.h>
#include <math.h>

#define BB 4
#define SS 64
#define DD 512
#define HH 8
#define DH 64
#define DFF 2048
#define LL 2
#define VV 32128
#define TT 16
#define NBLK 128

// ---------------- scratch (device globals) ----------------
__device__ float g_x[BB*SS*DD];
__device__ float g_h[BB*SS*DD];
__device__ float g_qkv[3*BB*SS*DD];
__device__ float g_ao[BB*SS*DD];
__device__ float g_ffn[BB*SS*DFF];
__device__ float g_hs[BB*SS*DD];
__device__ float g_ckv[2*LL*BB*SS*DD];   // cross K|V per layer
__device__ float g_ksc[LL*BB*TT*DD];     // self K cache
__device__ float g_vsc[LL*BB*TT*DD];     // self V cache
__device__ float g_dx[BB*DD];
__device__ float g_dq[BB*DD];
__device__ float g_da[BB*DD];
__device__ float g_dffn[BB*DFF];
__device__ float g_logits[BB*VV];
__device__ float g_bias[BB*SS];
__device__ float g_red_sum[BB];
__device__ unsigned long long g_red_key[BB];

// ---------------- grid barrier (sense-reversing, relative generation) -------
__device__ unsigned g_barA;
__device__ volatile unsigned g_barG;

__device__ __forceinline__ void gbar() {
    __syncthreads();
    if (threadIdx.x == 0) {
        unsigned gen = g_barG;
        __threadfence();
        if (atomicAdd(&g_barA, 1u) == NBLK - 1u) {
            g_barA = 0u;
            __threadfence();
            g_barG = gen + 1u;
        } else {
            while (g_barG == gen) { }
        }
        __threadfence();
    }
    __syncthreads();
}

__device__ __forceinline__ float warpSum(float v) {
#pragma unroll
    for (int o = 16; o > 0; o >>= 1) v += __shfl_xor_sync(0xffffffffu, v, o);
    return v;
}

// ---------------- embedding gather + encoder bias ----------------
__global__ void k_embed(const int* __restrict__ ids, const float* __restrict__ emb,
                        const float* __restrict__ mask) {
    int row = blockIdx.x;
    int id = ids[row];
    const float* e = emb + (size_t)id * DD;
    for (int d = threadIdx.x; d < DD; d += blockDim.x) g_x[row * DD + d] = e[d];
    if (threadIdx.x == 0) g_bias[row] = (1.0f - mask[row]) * -1e9f;
}

// ---------------- rmsnorm rows [M, DD] + fused buffer zeroing ----------------
__global__ void k_rmsnorm(const float* __restrict__ x, const float* __restrict__ w,
                          float* __restrict__ out, float* __restrict__ zbuf, int zn) {
    int row = blockIdx.x;
    const float* xr = x + (size_t)row * DD;
    float ss = 0.f;
    for (int i = threadIdx.x; i < DD; i += 256) { float v = xr[i]; ss += v * v; }
    ss = warpSum(ss);
    __shared__ float red[8];
    __shared__ float sscale;
    int lane = threadIdx.x & 31, wid = threadIdx.x >> 5;
    if (lane == 0) red[wid] = ss;
    __syncthreads();
    if (threadIdx.x == 0) {
        float s = 0.f;
        for (int i = 0; i < 8; i++) s += red[i];
        sscale = rsqrtf(s * (1.0f / DD) + 1e-6f);
    }
    __syncthreads();
    float sc = sscale;
    for (int i = threadIdx.x; i < DD; i += 256) out[(size_t)row * DD + i] = xr[i] * sc * w[i];
    if (zbuf) {
        int stride = gridDim.x * 256;
        for (int i = blockIdx.x * 256 + threadIdx.x; i < zn; i += stride) zbuf[i] = 0.f;
    }
}

// ---------------- encoder GEMM: split-K + multi-matrix fusion ----------------
__global__ void k_egemm3(const float* __restrict__ A,
                         const float* __restrict__ W0, const float* __restrict__ W1,
                         const float* __restrict__ W2,
                         float* __restrict__ C0, float* __restrict__ C1,
                         float* __restrict__ C2,
                         int N, int K, int KS, int reluA) {
    __shared__ __align__(16) float As[16][64];
    __shared__ __align__(16) float Ws[16][64];
    int zz = blockIdx.z;
    int mat = zz / KS, ks = zz - mat * KS;
    const float* W = (mat == 0) ? W0 : ((mat == 1) ? W1 : W2);
    float* C = (mat == 0) ? C0 : ((mat == 1) ? C1 : C2);
    int Kc = K / KS;
    int kbeg = ks * Kc;
    int tid = threadIdx.x;
    int tx = tid & 15, ty = tid >> 4;
    int bm = blockIdx.y * 64, bn = blockIdx.x * 64;
    int ar = tid >> 2, ac = (tid & 3) * 4;
    int wr = tid >> 4, wc = (tid & 15) * 4;
    float acc[4][4] = {};
    for (int k0 = kbeg; k0 < kbeg + Kc; k0 += 16) {
        float4 av = *(const float4*)(A + (size_t)(bm + ar) * K + k0 + ac);
        if (reluA) {
            av.x = fmaxf(av.x, 0.f); av.y = fmaxf(av.y, 0.f);
            av.z = fmaxf(av.z, 0.f); av.w = fmaxf(av.w, 0.f);
        }
        As[ac + 0][ar] = av.x; As[ac + 1][ar] = av.y; As[ac + 2][ar] = av.z; As[ac + 3][ar] = av.w;
        *(float4*)&Ws[wr][wc] = *(const float4*)(W + (size_t)(k0 + wr) * N + bn + wc);
        __syncthreads();
#pragma unroll
        for (int kk = 0; kk < 16; kk++) {
            float4 a = *(const float4*)&As[kk][ty * 4];
            float4 b = *(const float4*)&Ws[kk][tx * 4];
            acc[0][0] += a.x * b.x; acc[0][1] += a.x * b.y; acc[0][2] += a.x * b.z; acc[0][3] += a.x * b.w;
            acc[1][0] += a.y * b.x; acc[1][1] += a.y * b.y; acc[1][2] += a.y * b.z; acc[1][3] += a.y * b.w;
            acc[2][0] += a.z * b.x; acc[2][1] += a.z * b.y; acc[2][2] += a.z * b.z; acc[2][3] += a.z * b.w;
            acc[3][0] += a.w * b.x; acc[3][1] += a.w * b.y; acc[3][2] += a.w * b.z; acc[3][3] += a.w * b.w;
        }
        __syncthreads();
    }
#pragma unroll
    for (int i = 0; i < 4; i++) {
        int m = bm + ty * 4 + i;
#pragma unroll
        for (int j = 0; j < 4; j++)
            atomicAdd(&C[(size_t)m * N + bn + tx * 4 + j], acc[i][j]);
    }
}

// ---------------- encoder attention: one block per (b,h), full 64x64 tile ------------
__global__ __launch_bounds__(256) void k_enc_attn2(const float* __restrict__ q,
                                                   const float* __restrict__ k,
                                                   const float* __restrict__ v,
                                                   float* __restrict__ out) {
    __shared__ float qs[64 * 64];
    __shared__ float ks[64 * 64];
    int b = blockIdx.x >> 3, h = blockIdx.x & 7;
    int tid = threadIdx.x;
    size_t rowbase = ((size_t)b * SS) * DD + h * DH;
    for (int x = tid; x < 1024; x += 256) {
        int r = x >> 4, c4 = (x & 15) << 2;
        ((float4*)qs)[x] = *(const float4*)(q + rowbase + (size_t)r * DD + c4);
        ((float4*)ks)[x] = *(const float4*)(k + rowbase + (size_t)r * DD + c4);
    }
    __syncthreads();
    int i = tid >> 2, jg = (tid & 3) << 4;
    float sc[16];
    const float* qrow = qs + i * 64;
#pragma unroll
    for (int jj = 0; jj < 16; jj++) {
        const float* krow = ks + (jg + jj) * 64;
        float d = 0.f;
#pragma unroll
        for (int dd = 0; dd < 64; dd++) d += qrow[dd] * krow[dd];
        sc[jj] = d * 0.125f + g_bias[b * SS + jg + jj];
    }
    float m = -1e30f;
#pragma unroll
    for (int jj = 0; jj < 16; jj++) m = fmaxf(m, sc[jj]);
    m = fmaxf(m, __shfl_xor_sync(0xffffffffu, m, 1));
    m = fmaxf(m, __shfl_xor_sync(0xffffffffu, m, 2));
    float ssum = 0.f;
#pragma unroll
    for (int jj = 0; jj < 16; jj++) { sc[jj] = expf(sc[jj] - m); ssum += sc[jj]; }
    ssum += __shfl_xor_sync(0xffffffffu, ssum, 1);
    ssum += __shfl_xor_sync(0xffffffffu, ssum, 2);
    float inv = 1.f / ssum;
    __syncthreads();  // all reads of qs/ks done
#pragma unroll
    for (int jj = 0; jj < 16; jj++) qs[i * 64 + jg + jj] = sc[jj] * inv;
    for (int x = tid; x < 1024; x += 256) {
        int r = x >> 4, c4 = (x & 15) << 2;
        ((float4*)ks)[x] = *(const float4*)(v + rowbase + (size_t)r * DD + c4);
    }
    __syncthreads();
    int d0 = (tid & 3) << 4;
    float4 o4[4];
#pragma unroll
    for (int t4 = 0; t4 < 4; t4++) o4[t4] = make_float4(0.f, 0.f, 0.f, 0.f);
    const float* prow = qs + i * 64;
    for (int j = 0; j < 64; j++) {
        float p = prow[j];
        const float* vrow = ks + j * 64 + d0;
#pragma unroll
        for (int t4 = 0; t4 < 4; t4++) {
            float4 vv = *(const float4*)(vrow + t4 * 4);
            o4[t4].x += p * vv.x; o4[t4].y += p * vv.y;
            o4[t4].z += p * vv.z; o4[t4].w += p * vv.w;
        }
    }
    float* orow = out + rowbase + (size_t)i * DD + d0;
#pragma unroll
    for (int t4 = 0; t4 < 4; t4++) *(float4*)(orow + t4 * 4) = o4[t4];
}

// ---------------- decoder init ----------------
__global__ void k_dec_init(const float* __restrict__ emb) {
    int i = blockIdx.x * blockDim.x + threadIdx.x;
    if (i < BB * DD) g_dx[i] = emb[i & (DD - 1)];
}

// ---------------- fused rmsnorm into shared (256 threads) ----------------
__device__ __forceinline__ void load_norm(const float* __restrict__ x,
                                          const float* __restrict__ lnw,
                                          float* sh_h) {
    int tid = threadIdx.x;
    float ss[BB] = {0.f, 0.f, 0.f, 0.f};
    for (int i = tid; i < DD; i += 256) {
#pragma unroll
        for (int b = 0; b < BB; b++) {
            float v = x[b * DD + i];
            sh_h[b * DD + i] = v;
            ss[b] += v * v;
        }
    }
    __shared__ float sred[BB][8];
    __shared__ float sscale[BB];
    int lane = tid & 31, wid = tid >> 5;
#pragma unroll
    for (int b = 0; b < BB; b++) {
        float v = warpSum(ss[b]);
        if (lane == 0) sred[b][wid] = v;
    }
    __syncthreads();
    if (tid < BB) {
        float s = 0.f;
        for (int w = 0; w < 8; w++) s += sred[tid][w];
        sscale[tid] = rsqrtf(s * (1.0f / DD) + 1e-6f);
    }
    __syncthreads();
    for (int i = tid; i < DD; i += 256) {
        float w = lnw[i];
#pragma unroll
        for (int b = 0; b < BB; b++) sh_h[b * DD + i] *= sscale[b] * w;
    }
    __syncthreads();
}

// ---------------- in-block GEMV, 16 cols x 16 K-splits; result for tid<64 ----------
__device__ __forceinline__ float dgemv16(const float* __restrict__ sh_a, int K,
                                         const float* __restrict__ W, int ldw,
                                         int col0, float* part) {
    int tid = threadIdx.x;
    int c = tid & 15, s = tid >> 4;
    int Kc = K >> 4;
    const float* Wp = W + (size_t)(s * Kc) * ldw + col0 + c;
    const float* ap = sh_a + s * Kc;
    float a0 = 0.f, a1 = 0.f, a2 = 0.f, a3 = 0.f;
#pragma unroll 8
    for (int i = 0; i < Kc; i++) {
        float w = Wp[(size_t)i * ldw];
        a0 += ap[i] * w; a1 += ap[K + i] * w;
        a2 += ap[2 * K + i] * w; a3 += ap[3 * K + i] * w;
    }
    part[tid * 4 + 0] = a0; part[tid * 4 + 1] = a1;
    part[tid * 4 + 2] = a2; part[tid * 4 + 3] = a3;
    __syncthreads();
    float v = 0.f;
    if (tid < 64) {
        int cc = tid & 15, b = tid >> 4;
#pragma unroll
        for (int s2 = 0; s2 < 16; s2++) v += part[(s2 * 16 + cc) * 4 + b];
    }
    return v;
}

// ---------------- in-block GEMV, 32 cols x 8 K-splits; result for tid<128 ----------
__device__ __forceinline__ float dgemv32(const float* __restrict__ sh_a, int K,
                                         const float* __restrict__ W, int ldw,
                                         int col0, float* part) {
    int tid = threadIdx.x;
    int c = tid & 31, s = tid >> 5;
    int Kc = K >> 3;
    const float* Wp = W + (size_t)(s * Kc) * ldw + col0 + c;
    const float* ap = sh_a + s * Kc;
    float a0 = 0.f, a1 = 0.f, a2 = 0.f, a3 = 0.f;
#pragma unroll 8
    for (int i = 0; i < Kc; i++) {
        float w = Wp[(size_t)i * ldw];
        a0 += ap[i] * w; a1 += ap[K + i] * w;
        a2 += ap[2 * K + i] * w; a3 += ap[3 * K + i] * w;
    }
    part[tid * 4 + 0] = a0; part[tid * 4 + 1] = a1;
    part[tid * 4 + 2] = a2; part[tid * 4 + 3] = a3;
    __syncthreads();
    float v = 0.f;
    if (tid < 128) {
        int cc = tid & 31, b = tid >> 5;
#pragma unroll
        for (int s2 = 0; s2 < 8; s2++) v += part[(s2 * 32 + cc) * 4 + b];
    }
    return v;
}

// ============================================================================
// DECODE MEGAKERNEL: full 16-step incremental decode in one launch.
// ============================================================================
__global__ __launch_bounds__(256, 1) void k_decode(
    const float* __restrict__ dsq, const float* __restrict__ dsk,
    const float* __restrict__ dsv, const float* __restrict__ dso,
    const float* __restrict__ dln1,
    const float* __restrict__ dcq, const float* __restrict__ dco,
    const float* __restrict__ dln2,
    const float* __restrict__ dw1, const float* __restrict__ dw2,
    const float* __restrict__ dln3,
    const float* __restrict__ dlnf, const float* __restrict__ lmh,
    const float* __restrict__ emb,
    float* __restrict__ outp, float* __restrict__ outf) {
    __shared__ float sm[9216];  // 36KB, aliased per stage
    int blk = blockIdx.x, tid = threadIdx.x;

    for (int t = 0; t < TT; t++) {
        for (int l = 0; l < LL; l++) {
            size_t o2 = (size_t)l * DD * DD;
            const float* Wsq = dsq + o2; const float* Wsk = dsk + o2;
            const float* Wsv = dsv + o2; const float* Wso = dso + o2;
            const float* Wcq = dcq + o2; const float* Wco = dco + o2;
            const float* Ww1 = dw1 + (size_t)l * DD * DFF;
            const float* Ww2 = dw2 + (size_t)l * DFF * DD;
            float* ksl = g_ksc + (size_t)l * BB * TT * DD;
            float* vsl = g_vsc + (size_t)l * BB * TT * DD;
            const float* kcl = g_ckv + (size_t)(l * 2 + 0) * BB * SS * DD;
            const float* vcl = g_ckv + (size_t)(l * 2 + 1) * BB * SS * DD;

            // S1: norm(ln1) + QKV gemv, KV-cache append (96 blocks)
            if (blk < 96) {
                load_norm(g_dx, dln1 + l * DD, sm);
                int mat = blk >> 5, cb = blk & 31;
                const float* W = (mat == 0) ? Wsq : ((mat == 1) ? Wsk : Wsv);
                float v = dgemv16(sm, DD, W, DD, cb * 16, sm + 2048);
                if (tid < 64) {
                    int b = tid >> 4, col = cb * 16 + (tid & 15);
                    if (mat == 0) g_dq[b * DD + col] = v;
                    else if (mat == 1) ksl[((size_t)b * TT + t) * DD + col] = v;
                    else vsl[((size_t)b * TT + t) * DD + col] = v;
                }
            }
            gbar();

            // S2: self-attention (32 blocks)
            if (blk < 32) {
                int b = blk >> 3, h = blk & 7;
                float* qs = sm; float* at = sm + 64; float* ex = sm + 128;
                if (tid < 64) qs[tid] = g_dq[b * DD + h * DH + tid];
                __syncthreads();
                int nk = t + 1;
                if (tid < nk) {
                    const float* kr = ksl + ((size_t)b * TT + tid) * DD + h * DH;
                    float dot = 0.f;
#pragma unroll
                    for (int d = 0; d < DH; d++) dot += qs[d] * kr[d];
                    at[tid] = dot * 0.125f;
                }
                __syncthreads();
                float m = -1e30f;
                for (int j = 0; j < nk; j++) m = fmaxf(m, at[j]);
                if (tid < nk) ex[tid] = expf(at[tid] - m);
                __syncthreads();
                if (tid < 64) {
                    float s = 0.f;
                    for (int j = 0; j < nk; j++) s += ex[j];
                    const float* vb = vsl + (size_t)b * TT * DD + h * DH + tid;
                    float o = 0.f;
                    for (int j = 0; j < nk; j++) o += ex[j] * vb[(size_t)j * DD];
                    g_da[b * DD + h * DH + tid] = o / s;
                }
            }
            gbar();

            // S3: o-proj + residual (32 blocks)
            if (blk < 32) {
                for (int i = tid; i < DD; i += 256)
#pragma unroll
                    for (int b = 0; b < BB; b++) sm[b * DD + i] = g_da[b * DD + i];
                __syncthreads();
                float v = dgemv16(sm, DD, Wso, DD, blk * 16, sm + 2048);
                if (tid < 64) {
                    int b = tid >> 4, col = blk * 16 + (tid & 15);
                    g_dx[b * DD + col] += v;
                }
            }
            gbar();

            // S4: norm(ln2) + cq gemv (32 blocks)
            if (blk < 32) {
                load_norm(g_dx, dln2 + l * DD, sm);
                float v = dgemv16(sm, DD, Wcq, DD, blk * 16, sm + 2048);
                if (tid < 64) {
                    int b = tid >> 4, col = blk * 16 + (tid & 15);
                    g_dq[b * DD + col] = v;
                }
            }
            gbar();

            // S5: cross-attention (32 blocks)
            if (blk < 32) {
                int b = blk >> 3, h = blk & 7;
                float* qs = sm; float* at = sm + 64; float* ex = sm + 128;
                if (tid < 64) qs[tid] = g_dq[b * DD + h * DH + tid];
                __syncthreads();
                if (tid < 64) {
                    const float* kr = kcl + ((size_t)b * SS + tid) * DD + h * DH;
                    float dot = 0.f;
#pragma unroll
                    for (int d = 0; d < DH; d++) dot += qs[d] * kr[d];
                    at[tid] = dot * 0.125f + g_bias[b * SS + tid];
                }
                __syncthreads();
                float m = -1e30f;
                for (int j = 0; j < SS; j++) m = fmaxf(m, at[j]);
                if (tid < 64) ex[tid] = expf(at[tid] - m);
                __syncthreads();
                if (tid < 64) {
                    float s = 0.f;
                    for (int j = 0; j < SS; j++) s += ex[j];
                    const float* vb = vcl + (size_t)b * SS * DD + h * DH + tid;
                    float o = 0.f;
                    for (int j = 0; j < SS; j++) o += ex[j] * vb[(size_t)j * DD];
                    g_da[b * DD + h * DH + tid] = o / s;
                }
            }
            gbar();

            // S6: co-proj + residual (32 blocks)
            if (blk < 32) {
                for (int i = tid; i < DD; i += 256)
#pragma unroll
                    for (int b = 0; b < BB; b++) sm[b * DD + i] = g_da[b * DD + i];
                __syncthreads();
                float v = dgemv16(sm, DD, Wco, DD, blk * 16, sm + 2048);
                if (tid < 64) {
                    int b = tid >> 4, col = blk * 16 + (tid & 15);
                    g_dx[b * DD + col] += v;
                }
            }
            gbar();

            // S7: norm(ln3) + ffn1 + relu (64 blocks)
            if (blk < 64) {
                load_norm(g_dx, dln3 + l * DD, sm);
                float v = dgemv32(sm, DD, Ww1, DFF, blk * 32, sm + 2048);
                if (tid < 128) {
                    int b = tid >> 5, col = blk * 32 + (tid & 31);
                    g_dffn[b * DFF + col] = fmaxf(v, 0.f);
                }
            }
            gbar();

            // S8: ffn2 + residual (32 blocks)
            if (blk < 32) {
                for (int i = tid; i < DFF; i += 256)
#pragma unroll
                    for (int b = 0; b < BB; b++) sm[b * DFF + i] = g_dffn[b * DFF + i];
                __syncthreads();
                float v = dgemv16(sm, DFF, Ww2, DD, blk * 16, sm + 8192);
                if (tid < 64) {
                    int b = tid >> 4, col = blk * 16 + (tid & 15);
                    g_dx[b * DD + col] += v;
                }
            }
            gbar();
        }

        // S9: norm(lnf) + lm_head (all 128 blocks; 251 chunks of 128 cols)
        load_norm(g_dx, dlnf, sm);
        {
            float4* part4 = (float4*)(sm + 2048);
            int g = tid & 31, s = tid >> 5;
            for (int chunk = blk; chunk < 251; chunk += NBLK) {
                int col = chunk * 128 + (g << 2);
                float4 a0 = make_float4(0.f, 0.f, 0.f, 0.f), a1 = a0, a2 = a0, a3 = a0;
                const float* Wp = lmh + (size_t)(s * 64) * VV + col;
                const float* ap = sm + s * 64;
#pragma unroll 4
                for (int i = 0; i < 64; i++) {
                    float4 w = *(const float4*)(Wp + (size_t)i * VV);
                    float x0 = ap[i], x1 = ap[DD + i], x2 = ap[2 * DD + i], x3 = ap[3 * DD + i];
                    a0.x += x0 * w.x; a0.y += x0 * w.y; a0.z += x0 * w.z; a0.w += x0 * w.w;
                    a1.x += x1 * w.x; a1.y += x1 * w.y; a1.z += x1 * w.z; a1.w += x1 * w.w;
                    a2.x += x2 * w.x; a2.y += x2 * w.y; a2.z += x2 * w.z; a2.w += x2 * w.w;
                    a3.x += x3 * w.x; a3.y += x3 * w.y; a3.z += x3 * w.z; a3.w += x3 * w.w;
                }
                part4[tid * 4 + 0] = a0; part4[tid * 4 + 1] = a1;
                part4[tid * 4 + 2] = a2; part4[tid * 4 + 3] = a3;
                __syncthreads();
                if (tid < 128) {
                    int gg = tid & 31, b = tid >> 5;
                    float4 ts = make_float4(0.f, 0.f, 0.f, 0.f);
#pragma unroll
                    for (int s2 = 0; s2 < 8; s2++) {
                        float4 p = part4[(s2 * 32 + gg) * 4 + b];
                        ts.x += p.x; ts.y += p.y; ts.z += p.z; ts.w += p.w;
                    }
                    *(float4*)(g_logits + (size_t)b * VV + chunk * 128 + (gg << 2)) = ts;
                }
                __syncthreads();
            }
            if (blk == 0 && tid < BB) { g_red_sum[tid] = 0.f; g_red_key[tid] = 0ull; }
        }
        gbar();

        // S10: fused sumexp + argmax reduction (no max shift; logits ~ +-3)
        {
            int base = blk * 251;  // 128*251 == VV
            float psum[BB] = {0.f, 0.f, 0.f, 0.f};
            unsigned long long pkey[BB] = {0ull, 0ull, 0ull, 0ull};
            if (tid < 251) {
                int idx = base + tid;
#pragma unroll
                for (int b = 0; b < BB; b++) {
                    float lg = g_logits[(size_t)b * VV + idx];
                    psum[b] = expf(lg);
                    unsigned u = __float_as_uint(lg);
                    u = (u & 0x80000000u) ? ~u : (u | 0x80000000u);
                    pkey[b] = (((unsigned long long)u) << 32) | (unsigned)(~idx);
                }
            }
#pragma unroll
            for (int b = 0; b < BB; b++) {
                float s = warpSum(psum[b]);
                unsigned long long kk = pkey[b];
#pragma unroll
                for (int o = 16; o > 0; o >>= 1) {
                    unsigned long long ot = __shfl_xor_sync(0xffffffffu, kk, o);
                    if (ot > kk) kk = ot;
                }
                if ((tid & 31) == 0) {
                    atomicAdd(&g_red_sum[b], s);
                    atomicMax(&g_red_key[b], kk);
                }
            }
            if (blk == NBLK - 1)
                for (int i = tid; i < BB * DD; i += 256) g_dx[i] = 0.f;
        }
        gbar();

        // S11: write probs + pred flag + y = probs @ emb (all 128 blocks)
        {
            float invb[BB];
#pragma unroll
            for (int b = 0; b < BB; b++) invb[b] = 1.f / g_red_sum[b];
            int colgrp = blk & 3, chunk = blk >> 2;  // 32 chunks * 1004 rows == VV
            int base = chunk * 1004;
            float* pp = sm;
            for (int i = tid; i < 1004; i += 256) {
#pragma unroll
                for (int b = 0; b < BB; b++) {
                    float pv = expf(g_logits[(size_t)b * VV + base + i]) * invb[b];
                    pp[b * 1004 + i] = pv;
                    if (colgrp == 0) outp[((size_t)b * TT + t) * VV + base + i] = pv;
                }
            }
            __syncthreads();
            int g = tid & 31, s = tid >> 5;
            int col = (colgrp << 7) + (g << 2);
            float4 a0 = make_float4(0.f, 0.f, 0.f, 0.f), a1 = a0, a2 = a0, a3 = a0;
            for (int i = s; i < 1004; i += 8) {
                float4 e = *(const float4*)(emb + (size_t)(base + i) * DD + col);
                float p0 = pp[i], p1 = pp[1004 + i], p2 = pp[2008 + i], p3 = pp[3012 + i];
                a0.x += p0 * e.x; a0.y += p0 * e.y; a0.z += p0 * e.z; a0.w += p0 * e.w;
                a1.x += p1 * e.x; a1.y += p1 * e.y; a1.z += p1 * e.z; a1.w += p1 * e.w;
                a2.x += p2 * e.x; a2.y += p2 * e.y; a2.z += p2 * e.z; a2.w += p2 * e.w;
                a3.x += p3 * e.x; a3.y += p3 * e.y; a3.z += p3 * e.z; a3.w += p3 * e.w;
            }
            float4* part4 = (float4*)(sm + 4096);
            part4[tid * 4 + 0] = a0; part4[tid * 4 + 1] = a1;
            part4[tid * 4 + 2] = a2; part4[tid * 4 + 3] = a3;
            __syncthreads();
            if (tid < 128) {
                int gg = tid & 31, b = tid >> 5;
                float4 ts = make_float4(0.f, 0.f, 0.f, 0.f);
#pragma unroll
                for (int s2 = 0; s2 < 8; s2++) {
                    float4 p = part4[(s2 * 32 + gg) * 4 + b];
                    ts.x += p.x; ts.y += p.y; ts.z += p.z; ts.w += p.w;
                }
                int co = (colgrp << 7) + (gg << 2);
                atomicAdd(&g_dx[b * DD + co + 0], ts.x);
                atomicAdd(&g_dx[b * DD + co + 1], ts.y);
                atomicAdd(&g_dx[b * DD + co + 2], ts.z);
                atomicAdd(&g_dx[b * DD + co + 3], ts.w);
            }
            if (blk == 0 && tid < BB && outf) {
                unsigned idx = ~(unsigned)(g_red_key[tid] & 0xFFFFFFFFull);
                outf[tid * TT + t] = (idx == 0) ? 1.f : 0.f;
            }
        }
        gbar();
    }
}

// ============================================================================
extern "C" void kernel_launch(void* const* d_in, const int* in_sizes, int n_in,
                              void* d_out, int out_size) {
    const int*   ids  = (const int*)d_in[0];
    const float* mask = (const float*)d_in[1];
    const float* emb  = (const float*)d_in[2];
    const float* ewq  = (const float*)d_in[3];
    const float* ewk  = (const float*)d_in[4];
    const float* ewv  = (const float*)d_in[5];
    const float* ewo  = (const float*)d_in[6];
    const float* eln1 = (const float*)d_in[7];
    const float* ew1  = (const float*)d_in[8];
    const float* ew2  = (const float*)d_in[9];
    const float* eln2 = (const float*)d_in[10];
    const float* elnf = (const float*)d_in[11];
    const float* dsq  = (const float*)d_in[12];
    const float* dsk  = (const float*)d_in[13];
    const float* dsv  = (const float*)d_in[14];
    const float* dso  = (const float*)d_in[15];
    const float* dln1 = (const float*)d_in[16];
    const float* dcq  = (const float*)d_in[17];
    const float* dck  = (const float*)d_in[18];
    const float* dcv  = (const float*)d_in[19];
    const float* dco  = (const float*)d_in[20];
    const float* dln2 = (const float*)d_in[21];
    const float* dw1  = (const float*)d_in[22];
    const float* dw2  = (const float*)d_in[23];
    const float* dln3 = (const float*)d_in[24];
    const float* dlnf = (const float*)d_in[25];
    const float* lmh  = (const float*)d_in[26];

    float* outp = (float*)d_out;
    float* outf = (out_size >= BB * TT * VV + BB * TT) ? (outp + (size_t)BB * TT * VV) : nullptr;

    void* p;
    cudaGetSymbolAddress(&p, g_x);    float* px   = (float*)p;
    cudaGetSymbolAddress(&p, g_h);    float* ph   = (float*)p;
    cudaGetSymbolAddress(&p, g_qkv);  float* pqkv = (float*)p;
    cudaGetSymbolAddress(&p, g_ao);   float* pao  = (float*)p;
    cudaGetSymbolAddress(&p, g_ffn);  float* pffn = (float*)p;
    cudaGetSymbolAddress(&p, g_hs);   float* phs  = (float*)p;
    cudaGetSymbolAddress(&p, g_ckv);  float* pckv = (float*)p;

    const int M = BB * SS;   // 256
    const int MD = M * DD;   // 131072
    float* pq = pqkv;
    float* pk = pqkv + MD;
    float* pv = pqkv + 2 * MD;

    // ---------------- encoder ----------------
    k_embed<<<BB * SS, 128>>>(ids, emb, mask);
    for (int l = 0; l < LL; l++) {
        size_t o2 = (size_t)l * DD * DD;
        k_rmsnorm<<<M, 256>>>(px, eln1 + l * DD, ph, pqkv, 3 * MD);
        k_egemm3<<<dim3(8, 4, 6), 256>>>(ph, ewq + o2, ewk + o2, ewv + o2,
                                         pq, pk, pv, DD, DD, 2, 0);
        k_enc_attn2<<<BB * HH, 256>>>(pq, pk, pv, pao);
        k_egemm3<<<dim3(8, 4, 4), 256>>>(pao, ewo + o2, nullptr, nullptr,
                                         px, nullptr, nullptr, DD, DD, 4, 0);
        k_rmsnorm<<<M, 256>>>(px, eln2 + l * DD, ph, pffn, M * DFF);
        k_egemm3<<<dim3(32, 4, 2), 256>>>(ph, ew1 + (size_t)l * DD * DFF, nullptr, nullptr,
                                          pffn, nullptr, nullptr, DFF, DD, 2, 0);
        k_egemm3<<<dim3(8, 4, 8), 256>>>(pffn, ew2 + (size_t)l * DFF * DD, nullptr, nullptr,
                                         px, nullptr, nullptr, DD, DFF, 8, 1);
    }
    k_rmsnorm<<<M, 256>>>(px, elnf, phs, pckv, 2 * LL * MD);
    for (int l = 0; l < LL; l++) {
        size_t o2 = (size_t)l * DD * DD;
        float* kcl = pckv + (size_t)(l * 2 + 0) * MD;
        float* vcl = pckv + (size_t)(l * 2 + 1) * MD;
        k_egemm3<<<dim3(8, 4, 4), 256>>>(phs, dck + o2, dcv + o2, nullptr,
                                         kcl, vcl, nullptr, DD, DD, 2, 0);
    }

    // ---------------- decoder: single persistent megakernel ----------------
    k_dec_init<<<(BB * DD + 255) / 256, 256>>>(emb);
    k_decode<<<NBLK, 256>>>(dsq, dsk, dsv, dso, dln1, dcq, dco, dln2,
                            dw1, dw2, dln3, dlnf, lmh, emb, outp, outf);
}